// round 16
// baseline (speedup 1.0000x reference)
#include <cuda_runtime.h>
#include <math.h>
#include <stdint.h>

// Problem constants
#define BB 4
#define TT 4096
#define DD 1024
#define NC 512           // number of time chunks
#define LL (TT / NC)     // 8 timesteps per chunk
#define ROW (3 * DD)     // 3072 floats per (b,t)

// Scratch: per-chunk affine summaries and per-chunk initial states.
__device__ float g_A[NC * BB * DD];
__device__ float g_S[NC * BB * DD];
__device__ float g_H[NC * BB * DD];

// ---- fast transcendentals (MUFU.TANH) -------------------------------------
__device__ __forceinline__ float tanh_fast(float v) {
    float r;
    asm("tanh.approx.f32 %0, %1;" : "=f"(r) : "f"(v));
    return r;
}
// sigmoid(v) = 0.5*tanh(0.5v) + 0.5 ; 1-sigmoid(v) = 0.5 - 0.5*tanh(0.5v)

// ---- cache policies --------------------------------------------------------
__device__ __forceinline__ uint64_t pol_sticky75() {
    // 75% evict_last (stays in L2 for pass 3), 25% evict_first
    uint64_t p;
    asm("createpolicy.fractional.L2::evict_last.L2::evict_first.b64 %0, 0.75;"
        : "=l"(p));
    return p;
}
__device__ __forceinline__ uint64_t pol_evict_last() {
    uint64_t p;
    asm("createpolicy.fractional.L2::evict_last.b64 %0, 1.0;" : "=l"(p));
    return p;
}
__device__ __forceinline__ uint64_t pol_evict_first() {
    uint64_t p;
    asm("createpolicy.fractional.L2::evict_first.b64 %0, 1.0;" : "=l"(p));
    return p;
}
__device__ __forceinline__ float4 ldg_pol(const float* p, uint64_t pol) {
    float4 v;
    asm("ld.global.nc.L2::cache_hint.v4.f32 {%0,%1,%2,%3}, [%4], %5;"
        : "=f"(v.x), "=f"(v.y), "=f"(v.z), "=f"(v.w) : "l"(p), "l"(pol));
    return v;
}
__device__ __forceinline__ void stg_pol(float* p, float4 v, uint64_t pol) {
    asm volatile("st.global.L2::cache_hint.v4.f32 [%0], {%1,%2,%3,%4}, %5;"
                 :: "l"(p), "f"(v.x), "f"(v.y), "f"(v.z), "f"(v.w), "l"(pol));
}
__device__ __forceinline__ float4 ldg_cs(const float* p) {   // streaming, read-once
    float4 v;
    asm("ld.global.nc.cs.v4.f32 {%0,%1,%2,%3}, [%4];"
        : "=f"(v.x), "=f"(v.y), "=f"(v.z), "=f"(v.w) : "l"(p));
    return v;
}
__device__ __forceinline__ void stg_cs(float* p, float4 v) { // streaming store
    asm volatile("st.global.cs.v4.f32 [%0], {%1,%2,%3,%4};"
                 :: "l"(p), "f"(v.x), "f"(v.y), "f"(v.z), "f"(v.w));
}

// ---------------------------------------------------------------------------
// Pass 1: per-chunk summary. ip/ig fills 75% sticky; A/S scratch stores
// pinned evict_last so the sticky x set can't push the scratch out.
// ---------------------------------------------------------------------------
__global__ __launch_bounds__(256) void k_pass1(const float* __restrict__ x,
                                               const float* __restrict__ carry) {
    const int b = blockIdx.y;
    const int c = blockIdx.x;
    const int d = threadIdx.x * 4;

    const uint64_t pol  = pol_sticky75();
    const uint64_t polL = pol_evict_last();
    const float* xb = x + (long)(b * TT + c * LL) * ROW + d;

    float A[4] = {1.f, 1.f, 1.f, 1.f};
    float S[4] = {0.f, 0.f, 0.f, 0.f};

#pragma unroll
    for (int t = 0; t < LL; t++) {
        float4 ip4 = ldg_pol(xb + (long)t * ROW, pol);
        float4 ig4 = ldg_pol(xb + (long)t * ROW + DD, pol);
        float ip[4] = {ip4.x, ip4.y, ip4.z, ip4.w};
        float ig[4] = {ig4.x, ig4.y, ig4.z, ig4.w};
#pragma unroll
        for (int j = 0; j < 4; j++) {
            float tg  = tanh_fast(0.5f * ig[j]);
            float igs = fmaf(0.5f, tg, 0.5f);        // sigmoid(ig)
            float f   = fmaf(-0.5f, tg, 0.5f);       // 1 - sigmoid(ig)
            float sv  = tanh_fast(ip[j]) * igs;
            if (c == 0 && t == 0)
                sv += carry[b * DD + d + j] * f;
            A[j] = f * A[j];
            S[j] = fmaf(f, S[j], sv);
        }
    }

    const int idx = (c * BB + b) * DD + d;
    stg_pol(&g_A[idx], make_float4(A[0], A[1], A[2], A[3]), polL);
    stg_pol(&g_S[idx], make_float4(S[0], S[1], S[2], S[3]), polL);
}

// ---------------------------------------------------------------------------
// Pass 2: pipelined sequential scan over NC chunk summaries per channel.
// Launched with PDL; syncs on p1 before touching scratch.
// ---------------------------------------------------------------------------
#define PF 16
__global__ __launch_bounds__(32) void k_pass2(float* __restrict__ out) {
    cudaGridDependencySynchronize();   // wait for p1's writes

    const int b   = blockIdx.x >> 3;
    const int seg = blockIdx.x & 7;
    const int d   = seg * 128 + threadIdx.x * 4;

    const int stride4 = (BB * DD) / 4;
    const float4* __restrict__ pA = (const float4*)&g_A[b * DD + d];
    const float4* __restrict__ pS = (const float4*)&g_S[b * DD + d];
    float4* __restrict__ pH = (float4*)&g_H[b * DD + d];

    float4 bufA[PF], bufS[PF];
#pragma unroll
    for (int i = 0; i < PF; i++) {
        bufA[i] = pA[i * stride4];
        bufS[i] = pS[i * stride4];
    }

    float h0 = 0.f, h1 = 0.f, h2 = 0.f, h3 = 0.f;

#pragma unroll 1
    for (int c = 0; c < NC; c += PF) {
#pragma unroll
        for (int i = 0; i < PF; i++) {
            float4 A = bufA[i];
            float4 S = bufS[i];
            const int nc_ = c + PF + i;
            if (nc_ < NC) {                       // prefetch PF ahead
                bufA[i] = pA[nc_ * stride4];
                bufS[i] = pS[nc_ * stride4];
            }
            pH[(c + i) * stride4] = make_float4(h0, h1, h2, h3);
            h0 = fmaf(A.x, h0, S.x);
            h1 = fmaf(A.y, h1, S.y);
            h2 = fmaf(A.z, h2, S.z);
            h3 = fmaf(A.w, h3, S.w);
        }
    }
    // h_last
    *(float4*)(out + b * DD + d) = make_float4(h0, h1, h2, h3);
}

// ---------------------------------------------------------------------------
// Pass 3: replay each chunk; ip/ig reads use evict-first policy (hit the
// sticky lines once, then release them). og stays pure streaming.
// ---------------------------------------------------------------------------
__global__ __launch_bounds__(256) void k_pass3(const float* __restrict__ x,
                                               const float* __restrict__ carry,
                                               float* __restrict__ out) {
    const int b = blockIdx.y;
    const int c = blockIdx.x;
    const int d = threadIdx.x * 4;

    const uint64_t polf = pol_evict_first();
    const float* xb = x + (long)(b * TT + c * LL) * ROW + d;
    float* yb = out + (long)BB * DD /* skip h_last */
                    + (long)(b * TT + c * LL) * DD + d;

    // Prefetch first timestep from x (input buffer: no dependency on p1/p2)
    float4 ip0 = ldg_pol(xb, polf);
    float4 ig0 = ldg_pol(xb + DD, polf);
    float4 og0 = ldg_cs(xb + 2 * DD);

    cudaGridDependencySynchronize();   // now wait for p2's g_H

    const int idx = (c * BB + b) * DD + d;
    float4 h4 = *(const float4*)(&g_H[idx]);
    float h[4] = {h4.x, h4.y, h4.z, h4.w};

#pragma unroll
    for (int t = 0; t < LL; t++) {
        float4 ip4, ig4, og4;
        if (t == 0) { ip4 = ip0; ig4 = ig0; og4 = og0; }
        else {
            ip4 = ldg_pol(xb + (long)t * ROW, polf);
            ig4 = ldg_pol(xb + (long)t * ROW + DD, polf);
            og4 = ldg_cs(xb + (long)t * ROW + 2 * DD);
        }
        float ip[4] = {ip4.x, ip4.y, ip4.z, ip4.w};
        float ig[4] = {ig4.x, ig4.y, ig4.z, ig4.w};
        float og[4] = {og4.x, og4.y, og4.z, og4.w};
        float y[4];
#pragma unroll
        for (int j = 0; j < 4; j++) {
            float tg  = tanh_fast(0.5f * ig[j]);
            float igs = fmaf(0.5f, tg, 0.5f);
            float f   = fmaf(-0.5f, tg, 0.5f);
            float sv  = tanh_fast(ip[j]) * igs;
            if (c == 0 && t == 0)
                sv += carry[b * DD + d + j] * f;
            h[j] = fmaf(f, h[j], sv);
            float to  = tanh_fast(0.5f * og[j]);
            float ogs = fmaf(0.5f, to, 0.5f);
            y[j] = tanh_fast(h[j]) * ogs;
        }
        stg_cs(yb + (long)t * DD, make_float4(y[0], y[1], y[2], y[3]));
    }
}

extern "C" void kernel_launch(void* const* d_in, const int* in_sizes, int n_in,
                              void* d_out, int out_size) {
    const float* x     = (const float*)d_in[0];
    const float* carry = (const float*)d_in[1];
    float* out         = (float*)d_out;

    dim3 grid13(NC, BB);
    k_pass1<<<grid13, 256>>>(x, carry);

    cudaLaunchAttribute attr;
    attr.id = cudaLaunchAttributeProgrammaticStreamSerialization;
    attr.val.programmaticStreamSerializationAllowed = 1;

    {
        cudaLaunchConfig_t cfg = {};
        cfg.gridDim  = dim3(BB * 8);
        cfg.blockDim = dim3(32);
        cfg.attrs    = &attr;
        cfg.numAttrs = 1;
        cudaLaunchKernelEx(&cfg, k_pass2, out);
    }
    {
        cudaLaunchConfig_t cfg = {};
        cfg.gridDim  = grid13;
        cfg.blockDim = dim3(256);
        cfg.attrs    = &attr;
        cfg.numAttrs = 1;
        cudaLaunchKernelEx(&cfg, k_pass3, x, carry, out);
    }
}

// round 17
// speedup vs baseline: 1.0421x; 1.0421x over previous
#include <cuda_runtime.h>
#include <math.h>
#include <stdint.h>

// Problem constants
#define BB 4
#define TT 4096
#define DD 1024
#define NC 512           // number of time chunks
#define LL (TT / NC)     // 8 timesteps per chunk
#define ROW (3 * DD)     // 3072 floats per (b,t)

// Scratch: per-chunk affine summaries and per-chunk initial states.
__device__ float g_A[NC * BB * DD];
__device__ float g_S[NC * BB * DD];
__device__ float g_H[NC * BB * DD];

// ---- fast transcendentals (MUFU.TANH) -------------------------------------
__device__ __forceinline__ float tanh_fast(float v) {
    float r;
    asm("tanh.approx.f32 %0, %1;" : "=f"(r) : "f"(v));
    return r;
}
// sigmoid(v) = 0.5*tanh(0.5v) + 0.5 ; 1-sigmoid(v) = 0.5 - 0.5*tanh(0.5v)

// ---- cache policies --------------------------------------------------------
__device__ __forceinline__ uint64_t pol_half_sticky() {
    // 50% evict_last (stays in L2 for pass 3), 50% evict_first (streams out)
    uint64_t p;
    asm("createpolicy.fractional.L2::evict_last.L2::evict_first.b64 %0, 0.5;"
        : "=l"(p));
    return p;
}
__device__ __forceinline__ uint64_t pol_evict_first() {
    uint64_t p;
    asm("createpolicy.fractional.L2::evict_first.b64 %0, 1.0;" : "=l"(p));
    return p;
}
__device__ __forceinline__ float4 ldg_pol(const float* p, uint64_t pol) {
    float4 v;
    asm("ld.global.nc.L2::cache_hint.v4.f32 {%0,%1,%2,%3}, [%4], %5;"
        : "=f"(v.x), "=f"(v.y), "=f"(v.z), "=f"(v.w) : "l"(p), "l"(pol));
    return v;
}
__device__ __forceinline__ float4 ldg_cs(const float* p) {   // streaming, read-once
    float4 v;
    asm("ld.global.nc.cs.v4.f32 {%0,%1,%2,%3}, [%4];"
        : "=f"(v.x), "=f"(v.y), "=f"(v.z), "=f"(v.w) : "l"(p));
    return v;
}
__device__ __forceinline__ void stg_cs(float* p, float4 v) { // streaming store
    asm volatile("st.global.cs.v4.f32 [%0], {%1,%2,%3,%4};"
                 :: "l"(p), "f"(v.x), "f"(v.y), "f"(v.z), "f"(v.w));
}

// ---------------------------------------------------------------------------
// Pass 1: per-chunk summary. ip/ig fills are 50% sticky so pass 3 re-reads
// hit L2 for part of its ip/ig traffic.
// ---------------------------------------------------------------------------
__global__ __launch_bounds__(256) void k_pass1(const float* __restrict__ x,
                                               const float* __restrict__ carry) {
    const int b = blockIdx.y;
    const int c = blockIdx.x;
    const int d = threadIdx.x * 4;

    const uint64_t pol = pol_half_sticky();
    const float* xb = x + (long)(b * TT + c * LL) * ROW + d;

    float A[4] = {1.f, 1.f, 1.f, 1.f};
    float S[4] = {0.f, 0.f, 0.f, 0.f};

#pragma unroll
    for (int t = 0; t < LL; t++) {
        float4 ip4 = ldg_pol(xb + (long)t * ROW, pol);
        float4 ig4 = ldg_pol(xb + (long)t * ROW + DD, pol);
        float ip[4] = {ip4.x, ip4.y, ip4.z, ip4.w};
        float ig[4] = {ig4.x, ig4.y, ig4.z, ig4.w};
#pragma unroll
        for (int j = 0; j < 4; j++) {
            float tg  = tanh_fast(0.5f * ig[j]);
            float igs = fmaf(0.5f, tg, 0.5f);        // sigmoid(ig)
            float f   = fmaf(-0.5f, tg, 0.5f);       // 1 - sigmoid(ig)
            float sv  = tanh_fast(ip[j]) * igs;
            if (c == 0 && t == 0)
                sv += carry[b * DD + d + j] * f;
            A[j] = f * A[j];
            S[j] = fmaf(f, S[j], sv);
        }
    }

    const int idx = (c * BB + b) * DD + d;
    *(float4*)(&g_A[idx]) = make_float4(A[0], A[1], A[2], A[3]);
    *(float4*)(&g_S[idx]) = make_float4(S[0], S[1], S[2], S[3]);
}

// ---------------------------------------------------------------------------
// Pass 2: pipelined sequential scan over NC chunk summaries per channel.
// Launched with PDL; syncs on p1 before touching scratch.
// ---------------------------------------------------------------------------
#define PF 16
__global__ __launch_bounds__(32) void k_pass2(float* __restrict__ out) {
    cudaGridDependencySynchronize();   // wait for p1's writes

    const int b   = blockIdx.x >> 3;
    const int seg = blockIdx.x & 7;
    const int d   = seg * 128 + threadIdx.x * 4;

    const int stride4 = (BB * DD) / 4;
    const float4* __restrict__ pA = (const float4*)&g_A[b * DD + d];
    const float4* __restrict__ pS = (const float4*)&g_S[b * DD + d];
    float4* __restrict__ pH = (float4*)&g_H[b * DD + d];

    float4 bufA[PF], bufS[PF];
#pragma unroll
    for (int i = 0; i < PF; i++) {
        bufA[i] = pA[i * stride4];
        bufS[i] = pS[i * stride4];
    }

    float h0 = 0.f, h1 = 0.f, h2 = 0.f, h3 = 0.f;

#pragma unroll 1
    for (int c = 0; c < NC; c += PF) {
#pragma unroll
        for (int i = 0; i < PF; i++) {
            float4 A = bufA[i];
            float4 S = bufS[i];
            const int nc_ = c + PF + i;
            if (nc_ < NC) {                       // prefetch PF ahead
                bufA[i] = pA[nc_ * stride4];
                bufS[i] = pS[nc_ * stride4];
            }
            pH[(c + i) * stride4] = make_float4(h0, h1, h2, h3);
            h0 = fmaf(A.x, h0, S.x);
            h1 = fmaf(A.y, h1, S.y);
            h2 = fmaf(A.z, h2, S.z);
            h3 = fmaf(A.w, h3, S.w);
        }
    }
    // h_last
    *(float4*)(out + b * DD + d) = make_float4(h0, h1, h2, h3);
}

// ---------------------------------------------------------------------------
// Pass 3: replay each chunk in REVERSE chunk order (newest-written sticky
// lines read first); ip/ig reads hit-and-release via evict-first policy.
// ---------------------------------------------------------------------------
__global__ __launch_bounds__(256) void k_pass3(const float* __restrict__ x,
                                               const float* __restrict__ carry,
                                               float* __restrict__ out) {
    const int b = blockIdx.y;
    const int c = (NC - 1) - blockIdx.x;   // reverse dispatch order
    const int d = threadIdx.x * 4;

    const uint64_t polf = pol_evict_first();
    const float* xb = x + (long)(b * TT + c * LL) * ROW + d;
    float* yb = out + (long)BB * DD /* skip h_last */
                    + (long)(b * TT + c * LL) * DD + d;

    // Prefetch first timestep from x (input buffer: no dependency on p1/p2)
    float4 ip0 = ldg_pol(xb, polf);
    float4 ig0 = ldg_pol(xb + DD, polf);
    float4 og0 = ldg_cs(xb + 2 * DD);

    cudaGridDependencySynchronize();   // now wait for p2's g_H

    const int idx = (c * BB + b) * DD + d;
    float4 h4 = *(const float4*)(&g_H[idx]);
    float h[4] = {h4.x, h4.y, h4.z, h4.w};

#pragma unroll
    for (int t = 0; t < LL; t++) {
        float4 ip4, ig4, og4;
        if (t == 0) { ip4 = ip0; ig4 = ig0; og4 = og0; }
        else {
            ip4 = ldg_pol(xb + (long)t * ROW, polf);
            ig4 = ldg_pol(xb + (long)t * ROW + DD, polf);
            og4 = ldg_cs(xb + (long)t * ROW + 2 * DD);
        }
        float ip[4] = {ip4.x, ip4.y, ip4.z, ip4.w};
        float ig[4] = {ig4.x, ig4.y, ig4.z, ig4.w};
        float og[4] = {og4.x, og4.y, og4.z, og4.w};
        float y[4];
#pragma unroll
        for (int j = 0; j < 4; j++) {
            float tg  = tanh_fast(0.5f * ig[j]);
            float igs = fmaf(0.5f, tg, 0.5f);
            float f   = fmaf(-0.5f, tg, 0.5f);
            float sv  = tanh_fast(ip[j]) * igs;
            if (c == 0 && t == 0)
                sv += carry[b * DD + d + j] * f;
            h[j] = fmaf(f, h[j], sv);
            float to  = tanh_fast(0.5f * og[j]);
            float ogs = fmaf(0.5f, to, 0.5f);
            y[j] = tanh_fast(h[j]) * ogs;
        }
        stg_cs(yb + (long)t * DD, make_float4(y[0], y[1], y[2], y[3]));
    }
}

extern "C" void kernel_launch(void* const* d_in, const int* in_sizes, int n_in,
                              void* d_out, int out_size) {
    const float* x     = (const float*)d_in[0];
    const float* carry = (const float*)d_in[1];
    float* out         = (float*)d_out;

    dim3 grid13(NC, BB);
    k_pass1<<<grid13, 256>>>(x, carry);

    cudaLaunchAttribute attr;
    attr.id = cudaLaunchAttributeProgrammaticStreamSerialization;
    attr.val.programmaticStreamSerializationAllowed = 1;

    {
        cudaLaunchConfig_t cfg = {};
        cfg.gridDim  = dim3(BB * 8);
        cfg.blockDim = dim3(32);
        cfg.attrs    = &attr;
        cfg.numAttrs = 1;
        cudaLaunchKernelEx(&cfg, k_pass2, out);
    }
    {
        cudaLaunchConfig_t cfg = {};
        cfg.gridDim  = grid13;
        cfg.blockDim = dim3(256);
        cfg.attrs    = &attr;
        cfg.numAttrs = 1;
        cudaLaunchKernelEx(&cfg, k_pass3, x, carry, out);
    }
}